// round 8
// baseline (speedup 1.0000x reference)
#include <cuda_runtime.h>
#include <cstdint>

// Problem dims
#define B_    512
#define T_    128
#define ID_   128
#define HD_   256
#define G4_   1024   // 4*HD
#define OUTD_ 128
#define BT_   65536  // B*T

typedef unsigned long long ull;

// ---------------- scratch (static device globals; no allocation) ----------------
__device__ float g_Whp[2][2][264][512];               // [dir][half][k][dl*4+g]; rows 256 used, 8 pad
__device__ float g_Wip[2][ID_][G4_];                  // Wi with permuted cols: colp = half*512+dl*4+g
__device__ float g_bpp[2][G4_];                       // bias (bi+bh) in permuted col order
__device__ float g_gx[2][(size_t)BT_ * G4_];          // x-gates + bias, permuted cols, 512MB
__device__ float g_x1[(size_t)B_ * T_ * 2 * HD_];
__device__ float g_x2[(size_t)B_ * T_ * HD_];
__device__ float g_x3[(size_t)B_ * T_ * HD_];
__device__ float g_x4[(size_t)B_ * T_ * OUTD_];

// ---------------- helpers ----------------
__device__ __forceinline__ ull fma2(ull a, ull b, ull c) {
    ull d;
    asm("fma.rn.f32x2 %0, %1, %2, %3;" : "=l"(d) : "l"(a), "l"(b), "l"(c));
    return d;
}
__device__ __forceinline__ ull dupf(float v) {
    ull r; unsigned u = __float_as_uint(v);
    asm("mov.b64 %0, {%1, %1};" : "=l"(r) : "r"(u));
    return r;
}
__device__ __forceinline__ ull pack2(float a, float b) {
    ull r;
    asm("mov.b64 %0, {%1, %2};" : "=l"(r) : "r"(__float_as_uint(a)), "r"(__float_as_uint(b)));
    return r;
}
__device__ __forceinline__ float lo32(ull v) { return __uint_as_float((unsigned)v); }
__device__ __forceinline__ float hi32(ull v) { return __uint_as_float((unsigned)(v >> 32)); }
__device__ __forceinline__ float sigm(float x) { return 1.f / (1.f + __expf(-x)); }
__device__ __forceinline__ float tanhp(float x) { return fmaf(2.f, sigm(2.f * x), -1.f); }

#define CLUSTER_SYNC() do { \
    asm volatile("barrier.cluster.arrive.aligned;" ::: "memory"); \
    asm volatile("barrier.cluster.wait.aligned;" ::: "memory"); \
} while (0)

__device__ __forceinline__ void st_cluster64(unsigned addr, ull v) {
    asm volatile("st.shared::cluster.b64 [%0], %1;" :: "r"(addr), "l"(v) : "memory");
}

// ---------------- prep: pack Whp (gate-interleaved), permuted Wi + bias ----------------
__global__ void prep_kernel(const float* __restrict__ Wh_f, const float* __restrict__ Wh_r,
                            const float* __restrict__ Wi_f, const float* __restrict__ Wi_r,
                            const float* __restrict__ bi_f, const float* __restrict__ bh_f,
                            const float* __restrict__ bi_r, const float* __restrict__ bh_r) {
    int idx = blockIdx.x * blockDim.x + threadIdx.x;
    int stride = gridDim.x * blockDim.x;
    // Whp: [dir][half][k][dl*4+g] <- Wh[k][g*256 + half*128 + dl]
    const int whtotal = 2 * 2 * 256 * 512;
    for (int i = idx; i < whtotal; i += stride) {
        int dir = i / (2 * 256 * 512);
        int r = i % (2 * 256 * 512);
        int half = r / (256 * 512);
        int r2 = r % (256 * 512);
        int k = r2 >> 9, col = r2 & 511;
        int dl = col >> 2, g = col & 3;
        int sc = g * 256 + half * 128 + dl;
        const float* Wh = dir ? Wh_r : Wh_f;
        g_Whp[dir][half][k][col] = Wh[k * G4_ + sc];
    }
    // Wip: [dir][k][colp], colp = half*512 + dl*4 + g <- Wi[k][g*256 + half*128 + dl]
    const int witotal = 2 * ID_ * G4_;
    for (int i = idx; i < witotal; i += stride) {
        int dir = i / (ID_ * G4_);
        int r = i % (ID_ * G4_);
        int k = r >> 10, colp = r & 1023;
        int half = colp >> 9, dl = (colp >> 2) & 127, g = colp & 3;
        int sc = g * 256 + half * 128 + dl;
        const float* Wi = dir ? Wi_r : Wi_f;
        g_Wip[dir][k][colp] = Wi[k * G4_ + sc];
    }
    for (int i = idx; i < 2 * G4_; i += stride) {
        int dir = i >> 10, colp = i & 1023;
        int half = colp >> 9, dl = (colp >> 2) & 127, g = colp & 3;
        int sc = g * 256 + half * 128 + dl;
        g_bpp[dir][colp] = dir ? (bi_r[sc] + bh_r[sc]) : (bi_f[sc] + bh_f[sc]);
    }
}

// ---------------- persistent clustered recurrent LSTM (h @ Wh only) ----------------
// 128 CTAs x 512 thr = 64 clusters of 2. Cluster: dir = cid>>5, rows = (cid&31)*16..+16.
// Thread = (dl = tid&127, rg = tid>>7): hidden dim dl (4 gates) x rows rg*4..+4.
// No gate transpose: accumulators feed the cell update directly. One cluster sync/step.
#define HPAR  4112   // 4096 + 16 pad (k=256 prefetch overread)

__global__ __launch_bounds__(512, 1) __cluster_dims__(2, 1, 1)
void lstm_kernel() {
    extern __shared__ float smem[];
    float* sm_h = smem;   // [2][HPAR]: [k(dim)][16 rows], 16-float pad per parity

    const int tid = threadIdx.x;
    const int cid = blockIdx.x >> 1;
    const int dir = cid >> 5;
    const int b0 = (cid & 31) * 16;
    unsigned rank;
    asm("mov.u32 %0, %%cluster_ctarank;" : "=r"(rank));
    const int half = (int)rank;

    const int dl = tid & 127, rg = tid >> 7;
    const int ghd = half * 128 + dl;

    // weight base: thread's float4 (4 gates of dim dl) per k; row = 128 float4
    const float4* wbase = (const float4*)&g_Whp[dir][half][0][0] + dl;
    // gx base: rows (b0+rg*4+j), permuted col base half*512 + dl*4
    const float* gxbase = &g_gx[dir][0] + ((size_t)(b0 + rg * 4) * T_) * G4_ + half * 512 + dl * 4;

    // zero both h parity buffers (incl pad)
    for (int i = tid; i < 2 * HPAR; i += 512) sm_h[i] = 0.f;

    float cst[4];
#pragma unroll
    for (int j = 0; j < 4; j++) cst[j] = 0.f;

    __syncthreads();
    CLUSTER_SYNC();

#pragma unroll 1
    for (int t = 0; t < T_; t++) {
        const int ts = dir ? (T_ - 1 - t) : t;

        // x-gates for this thread's 4 rows (DRAM; consumed after GEMM)
        float4 gxv[4];
        {
            const float* gp = gxbase + (size_t)ts * G4_;
#pragma unroll
            for (int j = 0; j < 4; j++)
                gxv[j] = *(const float4*)(gp + (size_t)j * T_ * G4_);
        }

        // recurrent GEMM: dim dl x 4 gates x 4 rows over k=256
        ull acc[4][2];
#pragma unroll
        for (int g = 0; g < 4; g++) { acc[g][0] = 0ull; acc[g][1] = 0ull; }

        float4 wv[8];
#pragma unroll
        for (int p = 0; p < 8; p++) wv[p] = wbase[(size_t)p * 128];

        const float* hb = sm_h + (t & 1) * HPAR + rg * 4;
        ulonglong2 hc = *(const ulonglong2*)hb;

#pragma unroll 4
        for (int k = 0; k < 256; k++) {
            float4 w = wv[k & 7];
            wv[k & 7] = wbase[(size_t)(k + 8) * 128];          // ring (pad rows cover k>=256)
            ulonglong2 hn = *(const ulonglong2*)(hb + (k + 1) * 16); // pad covers k=255
            ull w0 = dupf(w.x), w1 = dupf(w.y), w2 = dupf(w.z), w3 = dupf(w.w);
            acc[0][0] = fma2(hc.x, w0, acc[0][0]); acc[0][1] = fma2(hc.y, w0, acc[0][1]);
            acc[1][0] = fma2(hc.x, w1, acc[1][0]); acc[1][1] = fma2(hc.y, w1, acc[1][1]);
            acc[2][0] = fma2(hc.x, w2, acc[2][0]); acc[2][1] = fma2(hc.y, w2, acc[2][1]);
            acc[3][0] = fma2(hc.x, w3, acc[3][0]); acc[3][1] = fma2(hc.y, w3, acc[3][1]);
            hc = hn;
        }

        // cell update directly from accumulators (no staging, no extra barrier)
        float hv[4];
#pragma unroll
        for (int j = 0; j < 4; j++) {
            int pr = j >> 1;
            float gf, gi, ga, go;
            if (j & 1) {
                gf = hi32(acc[0][pr]); gi = hi32(acc[1][pr]);
                ga = hi32(acc[2][pr]); go = hi32(acc[3][pr]);
            } else {
                gf = lo32(acc[0][pr]); gi = lo32(acc[1][pr]);
                ga = lo32(acc[2][pr]); go = lo32(acc[3][pr]);
            }
            gf += gxv[j].x; gi += gxv[j].y; ga += gxv[j].z; go += gxv[j].w;
            float f = sigm(gf), ii = sigm(gi), a = tanhp(ga), o = sigm(go);
            float cc = fmaf(f, cst[j], ii * a);
            cst[j] = cc;
            hv[j] = o * tanhp(cc);
        }

        // h -> own smem (next parity) + peer via DSMEM
        {
            float* hw = sm_h + ((t + 1) & 1) * HPAR + ghd * 16 + rg * 4;
            *(float4*)hw = make_float4(hv[0], hv[1], hv[2], hv[3]);
            unsigned la = (unsigned)__cvta_generic_to_shared(hw);
            unsigned pa;
            asm("mapa.shared::cluster.u32 %0, %1, %2;" : "=r"(pa) : "r"(la), "r"(rank ^ 1u));
            st_cluster64(pa, pack2(hv[0], hv[1]));
            st_cluster64(pa + 8, pack2(hv[2], hv[3]));
        }
        // h -> global x1 (dl consecutive within warp -> coalesced)
        {
            float* gx = g_x1 + ((size_t)(b0 + rg * 4) * T_ + t) * 512 + dir * 256 + ghd;
#pragma unroll
            for (int j = 0; j < 4; j++) gx[(size_t)j * T_ * 512] = hv[j];
        }

        CLUSTER_SYNC();   // single barrier per step
    }
}

// ---------------- generic fp32x2 GEMM with bias + optional leaky-relu ----------------
template <int ACT>
__global__ __launch_bounds__(256) void gemm_kernel(const float* __restrict__ A,
                                                   const float* __restrict__ W,
                                                   const float* __restrict__ bias,
                                                   float* __restrict__ C,
                                                   int M, int N, int K) {
    __shared__ __align__(16) float smA[16][64];
    __shared__ __align__(16) float smW[16][128];

    const int tid = threadIdx.x;
    const int n0 = blockIdx.x * 128;
    const int m0 = blockIdx.y * 64;
    const int col = (tid & 31) * 4;
    const int rg = (tid >> 5) * 8;

    ull acc[4][4];
#pragma unroll
    for (int rp = 0; rp < 4; rp++)
#pragma unroll
        for (int c = 0; c < 4; c++) acc[rp][c] = 0ull;

    const int la_r = tid >> 2;
    const int la_k = (tid & 3) * 4;
    const int lw_n = (tid & 31) * 4;
    const int lw_k = tid >> 5;

    for (int k0 = 0; k0 < K; k0 += 16) {
        float4 av = *(const float4*)&A[(size_t)(m0 + la_r) * K + k0 + la_k];
        smA[la_k + 0][la_r] = av.x;
        smA[la_k + 1][la_r] = av.y;
        smA[la_k + 2][la_r] = av.z;
        smA[la_k + 3][la_r] = av.w;
        *(float4*)&smW[lw_k][lw_n]     = *(const float4*)&W[(size_t)(k0 + lw_k) * N + n0 + lw_n];
        *(float4*)&smW[lw_k + 8][lw_n] = *(const float4*)&W[(size_t)(k0 + lw_k + 8) * N + n0 + lw_n];
        __syncthreads();

#pragma unroll
        for (int kk = 0; kk < 16; kk++) {
            float4 wvv = *(const float4*)&smW[kk][col];
            ull wd0 = dupf(wvv.x), wd1 = dupf(wvv.y), wd2 = dupf(wvv.z), wd3 = dupf(wvv.w);
#pragma unroll
            for (int rp = 0; rp < 4; rp++) {
                ull hp = *(const ull*)&smA[kk][rg + 2 * rp];
                acc[rp][0] = fma2(hp, wd0, acc[rp][0]);
                acc[rp][1] = fma2(hp, wd1, acc[rp][1]);
                acc[rp][2] = fma2(hp, wd2, acc[rp][2]);
                acc[rp][3] = fma2(hp, wd3, acc[rp][3]);
            }
        }
        __syncthreads();
    }

    const float4 bv = *(const float4*)&bias[n0 + col];
#pragma unroll
    for (int rp = 0; rp < 4; rp++) {
        const int row0 = m0 + rg + 2 * rp;
        float4 v0, v1;
        v0.x = lo32(acc[rp][0]) + bv.x; v0.y = lo32(acc[rp][1]) + bv.y;
        v0.z = lo32(acc[rp][2]) + bv.z; v0.w = lo32(acc[rp][3]) + bv.w;
        v1.x = hi32(acc[rp][0]) + bv.x; v1.y = hi32(acc[rp][1]) + bv.y;
        v1.z = hi32(acc[rp][2]) + bv.z; v1.w = hi32(acc[rp][3]) + bv.w;
        if (ACT) {
            v0.x = fmaxf(v0.x, 0.1f * v0.x); v0.y = fmaxf(v0.y, 0.1f * v0.y);
            v0.z = fmaxf(v0.z, 0.1f * v0.z); v0.w = fmaxf(v0.w, 0.1f * v0.w);
            v1.x = fmaxf(v1.x, 0.1f * v1.x); v1.y = fmaxf(v1.y, 0.1f * v1.y);
            v1.z = fmaxf(v1.z, 0.1f * v1.z); v1.w = fmaxf(v1.w, 0.1f * v1.w);
        }
        *(float4*)&C[(size_t)row0 * N + n0 + col]       = v0;
        *(float4*)&C[(size_t)(row0 + 1) * N + n0 + col] = v1;
    }
}

// ---------------- head ----------------
__global__ __launch_bounds__(256) void head_kernel(float* __restrict__ out) {
    const int row = blockIdx.x * blockDim.x + threadIdx.x;
    if (row >= B_ * T_) return;
    const float* x = g_x4 + (size_t)row * OUTD_;
    float* o = out + (size_t)row * OUTD_;

#pragma unroll 4
    for (int j = 0; j < 64; j++) o[j] = sigm(x[j]);

    {
        float e[8]; float mx = -1e30f;
#pragma unroll
        for (int j = 0; j < 8; j++) { e[j] = x[64 + j]; mx = fmaxf(mx, e[j]); }
        float ssum = 0.f;
#pragma unroll
        for (int j = 0; j < 8; j++) { e[j] = __expf(e[j] - mx); ssum += e[j]; }
        float inv = 1.f / ssum;
#pragma unroll
        for (int j = 0; j < 8; j++) o[64 + j] = e[j] * inv;
    }
    {
        float e[16]; float mx = -1e30f;
#pragma unroll
        for (int j = 0; j < 16; j++) { e[j] = x[72 + j]; mx = fmaxf(mx, e[j]); }
        float ssum = 0.f;
#pragma unroll
        for (int j = 0; j < 16; j++) { e[j] = __expf(e[j] - mx); ssum += e[j]; }
        float inv = 1.f / ssum;
#pragma unroll
        for (int j = 0; j < 16; j++) o[72 + j] = e[j] * inv;
    }
    {
        float e[40]; float mx = -1e30f;
#pragma unroll
        for (int j = 0; j < 40; j++) { e[j] = x[88 + j]; mx = fmaxf(mx, e[j]); }
        float ssum = 0.f;
#pragma unroll
        for (int j = 0; j < 40; j++) { e[j] = __expf(e[j] - mx); ssum += e[j]; }
        float inv = 1.f / ssum;
#pragma unroll
        for (int j = 0; j < 40; j++) o[88 + j] = e[j] * inv;
    }
}

// ---------------- launch ----------------
extern "C" void kernel_launch(void* const* d_in, const int* in_sizes, int n_in,
                              void* d_out, int out_size) {
    (void)in_sizes; (void)n_in; (void)out_size;
    const float* x0   = (const float*)d_in[0];
    const float* Wi_f = (const float*)d_in[1];
    const float* bi_f = (const float*)d_in[2];
    const float* Wh_f = (const float*)d_in[3];
    const float* bh_f = (const float*)d_in[4];
    const float* Wi_r = (const float*)d_in[5];
    const float* bi_r = (const float*)d_in[6];
    const float* Wh_r = (const float*)d_in[7];
    const float* bh_r = (const float*)d_in[8];
    const float* W1   = (const float*)d_in[9];
    const float* b1   = (const float*)d_in[10];
    const float* W2   = (const float*)d_in[11];
    const float* b2   = (const float*)d_in[12];
    const float* W3   = (const float*)d_in[13];
    const float* b3   = (const float*)d_in[14];
    float* out = (float*)d_out;

    float *p_x1, *p_x2, *p_x3, *p_x4, *p_gx, *p_bpp, *p_wip;
    cudaGetSymbolAddress((void**)&p_x1, g_x1);
    cudaGetSymbolAddress((void**)&p_x2, g_x2);
    cudaGetSymbolAddress((void**)&p_x3, g_x3);
    cudaGetSymbolAddress((void**)&p_x4, g_x4);
    cudaGetSymbolAddress((void**)&p_gx, g_gx);
    cudaGetSymbolAddress((void**)&p_bpp, g_bpp);
    cudaGetSymbolAddress((void**)&p_wip, g_Wip);

    prep_kernel<<<256, 256>>>(Wh_f, Wh_r, Wi_f, Wi_r, bi_f, bh_f, bi_r, bh_r);

    // precompute x-gates (bias folded, columns pre-permuted)
    gemm_kernel<0><<<dim3(G4_ / 128, BT_ / 64), 256>>>(x0, p_wip, p_bpp, p_gx,
                                                       BT_, G4_, ID_);
    gemm_kernel<0><<<dim3(G4_ / 128, BT_ / 64), 256>>>(x0, p_wip + (size_t)ID_ * G4_,
                                                       p_bpp + G4_,
                                                       p_gx + (size_t)BT_ * G4_,
                                                       BT_, G4_, ID_);
    lstm_kernel<<<128, 512, 2 * HPAR * 4>>>();

    const int M = B_ * T_;
    gemm_kernel<1><<<dim3(HD_ / 128, M / 64), 256>>>(p_x1, W1, b1, p_x2, M, HD_, 2 * HD_);
    gemm_kernel<1><<<dim3(HD_ / 128, M / 64), 256>>>(p_x2, W2, b2, p_x3, M, HD_, HD_);
    gemm_kernel<0><<<dim3(OUTD_ / 128, M / 64), 256>>>(p_x3, W3, b3, p_x4, M, OUTD_, HD_);
    head_kernel<<<(M + 255) / 256, 256>>>(out);
}

// round 9
// speedup vs baseline: 1.3713x; 1.3713x over previous
#include <cuda_runtime.h>
#include <cstdint>

// Problem dims
#define B_    512
#define T_    128
#define ID_   128
#define HD_   256
#define G4_   1024   // 4*HD
#define OUTD_ 128
#define BT_   65536  // B*T
#define HPAD  68     // padded row length for sm_h (16B-aligned, conflict-free)

typedef unsigned long long ull;

// ---------------- scratch (static device globals; no allocation) ----------------
__device__ float g_Whg[2][8][256][128];               // [dir][q][k][dll*4+g]
__device__ float g_Wip[2][ID_][G4_];                  // Wi, permuted cols colp = dl*4+g
__device__ float g_bpp[2][G4_];                       // bias (bi+bh), permuted cols
__device__ float g_gx[2][(size_t)BT_ * G4_];          // x-gates + bias, permuted cols
__device__ float g_hx[2][2][8][256][64];              // [parity][dir][rg][dim][row] exchange
__device__ float g_x1[(size_t)B_ * T_ * 2 * HD_];
__device__ float g_x2[(size_t)B_ * T_ * HD_];
__device__ float g_x3[(size_t)B_ * T_ * HD_];
__device__ float g_x4[(size_t)B_ * T_ * OUTD_];

// ---------------- helpers ----------------
__device__ __forceinline__ ull fma2(ull a, ull b, ull c) {
    ull d;
    asm("fma.rn.f32x2 %0, %1, %2, %3;" : "=l"(d) : "l"(a), "l"(b), "l"(c));
    return d;
}
__device__ __forceinline__ ull dupf(float v) {
    ull r; unsigned u = __float_as_uint(v);
    asm("mov.b64 %0, {%1, %1};" : "=l"(r) : "r"(u));
    return r;
}
__device__ __forceinline__ float lo32(ull v) { return __uint_as_float((unsigned)v); }
__device__ __forceinline__ float hi32(ull v) { return __uint_as_float((unsigned)(v >> 32)); }
__device__ __forceinline__ float sigm(float x) { return 1.f / (1.f + __expf(-x)); }
__device__ __forceinline__ float tanhp(float x) { return fmaf(2.f, sigm(2.f * x), -1.f); }

__device__ __forceinline__ void cpa16(unsigned dsm, const void* g) {
    asm volatile("{ .reg .u64 ga; cvta.to.global.u64 ga, %1; "
                 "cp.async.cg.shared.global [%0], [ga], 16; }"
                 :: "r"(dsm), "l"(g) : "memory");
}
#define CPA_COMMIT() asm volatile("cp.async.commit_group;" ::: "memory")
#define CPA_WAIT0()  asm volatile("cp.async.wait_group 0;" ::: "memory")

#define CLUSTER_SYNC() do { \
    asm volatile("barrier.cluster.arrive.aligned;" ::: "memory"); \
    asm volatile("barrier.cluster.wait.aligned;" ::: "memory"); \
} while (0)

// ---------------- prep: pack Whg/Wip/bias (gate-interleaved), zero h exchange ----------------
__global__ void prep_kernel(const float* __restrict__ Wh_f, const float* __restrict__ Wh_r,
                            const float* __restrict__ Wi_f, const float* __restrict__ Wi_r,
                            const float* __restrict__ bi_f, const float* __restrict__ bh_f,
                            const float* __restrict__ bi_r, const float* __restrict__ bh_r) {
    int idx = blockIdx.x * blockDim.x + threadIdx.x;
    int stride = gridDim.x * blockDim.x;
    // Whg[dir][q][k][dll*4+g] <- Wh[k][g*256 + q*32 + dll]
    const int whtotal = 2 * 8 * 256 * 128;
    for (int i = idx; i < whtotal; i += stride) {
        int dirq = i / (256 * 128);
        int dir = dirq >> 3, q = dirq & 7;
        int r = i % (256 * 128);
        int k = r >> 7, col = r & 127;
        int dll = col >> 2, g = col & 3;
        int sc = g * 256 + q * 32 + dll;
        const float* Wh = dir ? Wh_r : Wh_f;
        g_Whg[dir][q][k][col] = Wh[k * G4_ + sc];
    }
    // Wip[dir][k][colp], colp = dl*4+g <- Wi[k][g*256 + dl]
    const int witotal = 2 * ID_ * G4_;
    for (int i = idx; i < witotal; i += stride) {
        int dir = i / (ID_ * G4_);
        int r = i % (ID_ * G4_);
        int k = r >> 10, colp = r & 1023;
        int dl = colp >> 2, g = colp & 3;
        int sc = g * 256 + dl;
        const float* Wi = dir ? Wi_r : Wi_f;
        g_Wip[dir][k][colp] = Wi[k * G4_ + sc];
    }
    for (int i = idx; i < 2 * G4_; i += stride) {
        int dir = i >> 10, colp = i & 1023;
        int dl = colp >> 2, g = colp & 3;
        int sc = g * 256 + dl;
        g_bpp[dir][colp] = dir ? (bi_r[sc] + bh_r[sc]) : (bi_f[sc] + bh_f[sc]);
    }
    // zero parity-0 h exchange buffer
    float* hz = &g_hx[0][0][0][0][0];
    for (int i = idx; i < 2 * 8 * 256 * 64; i += stride) hz[i] = 0.f;
}

// ---------------- persistent clustered recurrent LSTM, SMEM-resident weights ----------------
// 128 CTAs x 512 thr = 16 clusters of 8. Cluster cid: dir = cid>>3, rows = (cid&7)*64..+64.
// CTA rank q owns gate-cols for dims [q*32, q*32+32) x 4 gates; weights 128KB in smem for
// the whole kernel. h exchanged via L2 ping-pong + one cluster barrier per step.
__global__ __launch_bounds__(512, 1) __cluster_dims__(8, 1, 1)
void lstm_kernel() {
    extern __shared__ float sm[];
    float* sm_w = sm;              // [256][128] = 128KB, resident
    float* sm_h = sm + 32768;      // [256][HPAD] = 68KB (h staging, padded)

    const int tid = threadIdx.x;
    const int cid = blockIdx.x >> 3;
    const int dir = cid >> 3;
    const int rg = cid & 7;
    const int b0 = rg * 64;
    unsigned rank;
    asm("mov.u32 %0, %%cluster_ctarank;" : "=r"(rank));
    const int q = (int)rank;

    const int dll = tid & 31;      // lane = local dim
    const int rgrp = tid >> 5;     // warp = row group (4 rows)
    const int dimg = q * 32 + dll;

    const unsigned dbw = (unsigned)__cvta_generic_to_shared(sm_w);
    const unsigned dbh = (unsigned)__cvta_generic_to_shared(sm_h);

    // load weight slice into smem (once)
    {
        const float* wsrc = &g_Whg[dir][q][0][0];
        for (int i = tid; i < 8192; i += 512)
            cpa16(dbw + (unsigned)i * 16, wsrc + (size_t)i * 4);
        CPA_COMMIT();
    }

    // gx base: rows b0 + rgrp*4 + j, permuted col dimg*4
    const float* gx0 = &g_gx[dir][0] + ((size_t)(b0 + rgrp * 4) * T_) * G4_ + dimg * 4;

    float cst[4];
#pragma unroll
    for (int j = 0; j < 4; j++) cst[j] = 0.f;

    CPA_WAIT0();
    __syncthreads();

#pragma unroll 1
    for (int t = 0; t < T_; t++) {
        const int par = t & 1;
        const int ts = dir ? (T_ - 1 - t) : t;

        // bulk-load h(t) [256 dims][64 rows] from exchange buffer into padded smem
        {
            const float* hsrc = &g_hx[par][dir][rg][0][0];
#pragma unroll
            for (int u = 0; u < 8; u++) {
                int i = tid + 512 * u;
                int dim = i >> 4, ch = i & 15;
                cpa16(dbh + (unsigned)(dim * HPAD + ch * 4) * 4, hsrc + (size_t)i * 4);
            }
            CPA_COMMIT();
        }
        // issue x-gate loads (overlap cp.async wait + GEMM; consumed at update)
        float4 gxv[4];
        {
            const float* gp = gx0 + (size_t)ts * G4_;
#pragma unroll
            for (int j = 0; j < 4; j++)
                gxv[j] = *(const float4*)(gp + (size_t)j * T_ * G4_);
        }
        CPA_WAIT0();
        __syncthreads();

        // GEMM: dim dimg x 4 gates x 4 rows over k=256, all-smem operands
        ull acc[4][2];
#pragma unroll
        for (int g = 0; g < 4; g++) { acc[g][0] = 0ull; acc[g][1] = 0ull; }
        const float* wp = sm_w + dll * 4;
        const float* hp = sm_h + rgrp * 4;
#pragma unroll 8
        for (int k = 0; k < 256; k++) {
            ulonglong2 h2 = *(const ulonglong2*)(hp + k * HPAD);   // broadcast within warp
            float4 w = *(const float4*)(wp + k * 128);             // conflict-free
            ull w0 = dupf(w.x), w1 = dupf(w.y), w2 = dupf(w.z), w3 = dupf(w.w);
            acc[0][0] = fma2(h2.x, w0, acc[0][0]); acc[0][1] = fma2(h2.y, w0, acc[0][1]);
            acc[1][0] = fma2(h2.x, w1, acc[1][0]); acc[1][1] = fma2(h2.y, w1, acc[1][1]);
            acc[2][0] = fma2(h2.x, w2, acc[2][0]); acc[2][1] = fma2(h2.y, w2, acc[2][1]);
            acc[3][0] = fma2(h2.x, w3, acc[3][0]); acc[3][1] = fma2(h2.y, w3, acc[3][1]);
        }

        // cell update in-thread: rows rgrp*4 + j, dim dimg
        float hv[4];
#pragma unroll
        for (int j = 0; j < 4; j++) {
            int pr = j >> 1;
            float gf, gi, ga, go;
            if (j & 1) {
                gf = hi32(acc[0][pr]); gi = hi32(acc[1][pr]);
                ga = hi32(acc[2][pr]); go = hi32(acc[3][pr]);
            } else {
                gf = lo32(acc[0][pr]); gi = lo32(acc[1][pr]);
                ga = lo32(acc[2][pr]); go = lo32(acc[3][pr]);
            }
            gf += gxv[j].x; gi += gxv[j].y; ga += gxv[j].z; go += gxv[j].w;
            float f = sigm(gf), ii = sigm(gi), a = tanhp(ga), o = sigm(go);
            float cc = fmaf(f, cst[j], ii * a);
            cst[j] = cc;
            hv[j] = o * tanhp(cc);
        }

        // h -> global x1 (lanes = consecutive dims -> coalesced)
        {
            float* gx1p = g_x1 + ((size_t)(b0 + rgrp * 4) * T_ + t) * 512 + dir * 256 + dimg;
#pragma unroll
            for (int j = 0; j < 4; j++) gx1p[(size_t)j * T_ * 512] = hv[j];
        }

        __syncthreads();   // all GEMM reads of sm_h complete
        // bounce own h block through smem for coalesced exchange store
        *(float4*)(sm_h + dimg * HPAD + rgrp * 4) = make_float4(hv[0], hv[1], hv[2], hv[3]);
        __syncthreads();
        {
            float* hdst = &g_hx[par ^ 1][dir][rg][q * 32][0];
            int diml = tid >> 4, r0 = (tid & 15) * 4;
            float4 v = *(const float4*)(sm_h + (q * 32 + diml) * HPAD + r0);
            *(float4*)(hdst + diml * 64 + r0) = v;
        }
        __threadfence();
        CLUSTER_SYNC();
    }
}

// ---------------- generic fp32x2 GEMM with bias + optional leaky-relu ----------------
template <int ACT>
__global__ __launch_bounds__(256) void gemm_kernel(const float* __restrict__ A,
                                                   const float* __restrict__ W,
                                                   const float* __restrict__ bias,
                                                   float* __restrict__ C,
                                                   int M, int N, int K) {
    __shared__ __align__(16) float smA[16][64];
    __shared__ __align__(16) float smW[16][128];

    const int tid = threadIdx.x;
    const int n0 = blockIdx.x * 128;
    const int m0 = blockIdx.y * 64;
    const int col = (tid & 31) * 4;
    const int rg = (tid >> 5) * 8;

    ull acc[4][4];
#pragma unroll
    for (int rp = 0; rp < 4; rp++)
#pragma unroll
        for (int c = 0; c < 4; c++) acc[rp][c] = 0ull;

    const int la_r = tid >> 2;
    const int la_k = (tid & 3) * 4;
    const int lw_n = (tid & 31) * 4;
    const int lw_k = tid >> 5;

    for (int k0 = 0; k0 < K; k0 += 16) {
        float4 av = *(const float4*)&A[(size_t)(m0 + la_r) * K + k0 + la_k];
        smA[la_k + 0][la_r] = av.x;
        smA[la_k + 1][la_r] = av.y;
        smA[la_k + 2][la_r] = av.z;
        smA[la_k + 3][la_r] = av.w;
        *(float4*)&smW[lw_k][lw_n]     = *(const float4*)&W[(size_t)(k0 + lw_k) * N + n0 + lw_n];
        *(float4*)&smW[lw_k + 8][lw_n] = *(const float4*)&W[(size_t)(k0 + lw_k + 8) * N + n0 + lw_n];
        __syncthreads();

#pragma unroll
        for (int kk = 0; kk < 16; kk++) {
            float4 wvv = *(const float4*)&smW[kk][col];
            ull wd0 = dupf(wvv.x), wd1 = dupf(wvv.y), wd2 = dupf(wvv.z), wd3 = dupf(wvv.w);
#pragma unroll
            for (int rp = 0; rp < 4; rp++) {
                ull hp = *(const ull*)&smA[kk][rg + 2 * rp];
                acc[rp][0] = fma2(hp, wd0, acc[rp][0]);
                acc[rp][1] = fma2(hp, wd1, acc[rp][1]);
                acc[rp][2] = fma2(hp, wd2, acc[rp][2]);
                acc[rp][3] = fma2(hp, wd3, acc[rp][3]);
            }
        }
        __syncthreads();
    }

    const float4 bv = *(const float4*)&bias[n0 + col];
#pragma unroll
    for (int rp = 0; rp < 4; rp++) {
        const int row0 = m0 + rg + 2 * rp;
        float4 v0, v1;
        v0.x = lo32(acc[rp][0]) + bv.x; v0.y = lo32(acc[rp][1]) + bv.y;
        v0.z = lo32(acc[rp][2]) + bv.z; v0.w = lo32(acc[rp][3]) + bv.w;
        v1.x = hi32(acc[rp][0]) + bv.x; v1.y = hi32(acc[rp][1]) + bv.y;
        v1.z = hi32(acc[rp][2]) + bv.z; v1.w = hi32(acc[rp][3]) + bv.w;
        if (ACT) {
            v0.x = fmaxf(v0.x, 0.1f * v0.x); v0.y = fmaxf(v0.y, 0.1f * v0.y);
            v0.z = fmaxf(v0.z, 0.1f * v0.z); v0.w = fmaxf(v0.w, 0.1f * v0.w);
            v1.x = fmaxf(v1.x, 0.1f * v1.x); v1.y = fmaxf(v1.y, 0.1f * v1.y);
            v1.w = fmaxf(v1.w, 0.1f * v1.w); v1.z = fmaxf(v1.z, 0.1f * v1.z);
        }
        *(float4*)&C[(size_t)row0 * N + n0 + col]       = v0;
        *(float4*)&C[(size_t)(row0 + 1) * N + n0 + col] = v1;
    }
}

// ---------------- head ----------------
__global__ __launch_bounds__(256) void head_kernel(float* __restrict__ out) {
    const int row = blockIdx.x * blockDim.x + threadIdx.x;
    if (row >= B_ * T_) return;
    const float* x = g_x4 + (size_t)row * OUTD_;
    float* o = out + (size_t)row * OUTD_;

#pragma unroll 4
    for (int j = 0; j < 64; j++) o[j] = sigm(x[j]);

    {
        float e[8]; float mx = -1e30f;
#pragma unroll
        for (int j = 0; j < 8; j++) { e[j] = x[64 + j]; mx = fmaxf(mx, e[j]); }
        float ssum = 0.f;
#pragma unroll
        for (int j = 0; j < 8; j++) { e[j] = __expf(e[j] - mx); ssum += e[j]; }
        float inv = 1.f / ssum;
#pragma unroll
        for (int j = 0; j < 8; j++) o[64 + j] = e[j] * inv;
    }
    {
        float e[16]; float mx = -1e30f;
#pragma unroll
        for (int j = 0; j < 16; j++) { e[j] = x[72 + j]; mx = fmaxf(mx, e[j]); }
        float ssum = 0.f;
#pragma unroll
        for (int j = 0; j < 16; j++) { e[j] = __expf(e[j] - mx); ssum += e[j]; }
        float inv = 1.f / ssum;
#pragma unroll
        for (int j = 0; j < 16; j++) o[72 + j] = e[j] * inv;
    }
    {
        float e[40]; float mx = -1e30f;
#pragma unroll
        for (int j = 0; j < 40; j++) { e[j] = x[88 + j]; mx = fmaxf(mx, e[j]); }
        float ssum = 0.f;
#pragma unroll
        for (int j = 0; j < 40; j++) { e[j] = __expf(e[j] - mx); ssum += e[j]; }
        float inv = 1.f / ssum;
#pragma unroll
        for (int j = 0; j < 40; j++) o[88 + j] = e[j] * inv;
    }
}

// ---------------- launch ----------------
extern "C" void kernel_launch(void* const* d_in, const int* in_sizes, int n_in,
                              void* d_out, int out_size) {
    (void)in_sizes; (void)n_in; (void)out_size;
    const float* x0   = (const float*)d_in[0];
    const float* Wi_f = (const float*)d_in[1];
    const float* bi_f = (const float*)d_in[2];
    const float* Wh_f = (const float*)d_in[3];
    const float* bh_f = (const float*)d_in[4];
    const float* Wi_r = (const float*)d_in[5];
    const float* bi_r = (const float*)d_in[6];
    const float* Wh_r = (const float*)d_in[7];
    const float* bh_r = (const float*)d_in[8];
    const float* W1   = (const float*)d_in[9];
    const float* b1   = (const float*)d_in[10];
    const float* W2   = (const float*)d_in[11];
    const float* b2   = (const float*)d_in[12];
    const float* W3   = (const float*)d_in[13];
    const float* b3   = (const float*)d_in[14];
    float* out = (float*)d_out;

    float *p_x1, *p_x2, *p_x3, *p_x4, *p_gx, *p_bpp, *p_wip;
    cudaGetSymbolAddress((void**)&p_x1, g_x1);
    cudaGetSymbolAddress((void**)&p_x2, g_x2);
    cudaGetSymbolAddress((void**)&p_x3, g_x3);
    cudaGetSymbolAddress((void**)&p_x4, g_x4);
    cudaGetSymbolAddress((void**)&p_gx, g_gx);
    cudaGetSymbolAddress((void**)&p_bpp, g_bpp);
    cudaGetSymbolAddress((void**)&p_wip, g_Wip);

    static bool attr_set = false;
    if (!attr_set) {
        cudaFuncSetAttribute(lstm_kernel, cudaFuncAttributeMaxDynamicSharedMemorySize,
                             131072 + 256 * HPAD * 4);
        attr_set = true;
    }

    prep_kernel<<<256, 256>>>(Wh_f, Wh_r, Wi_f, Wi_r, bi_f, bh_f, bi_r, bh_r);

    // precompute x-gates (bias folded, columns pre-permuted to dl*4+g)
    gemm_kernel<0><<<dim3(G4_ / 128, BT_ / 64), 256>>>(x0, p_wip, p_bpp, p_gx,
                                                       BT_, G4_, ID_);
    gemm_kernel<0><<<dim3(G4_ / 128, BT_ / 64), 256>>>(x0, p_wip + (size_t)ID_ * G4_,
                                                       p_bpp + G4_,
                                                       p_gx + (size_t)BT_ * G4_,
                                                       BT_, G4_, ID_);
    lstm_kernel<<<128, 512, 131072 + 256 * HPAD * 4>>>();

    const int M = B_ * T_;
    gemm_kernel<1><<<dim3(HD_ / 128, M / 64), 256>>>(p_x1, W1, b1, p_x2, M, HD_, 2 * HD_);
    gemm_kernel<1><<<dim3(HD_ / 128, M / 64), 256>>>(p_x2, W2, b2, p_x3, M, HD_, HD_);
    gemm_kernel<0><<<dim3(OUTD_ / 128, M / 64), 256>>>(p_x3, W3, b3, p_x4, M, OUTD_, HD_);
    head_kernel<<<(M + 255) / 256, 256>>>(out);
}

// round 10
// speedup vs baseline: 2.1750x; 1.5861x over previous
#include <cuda_runtime.h>
#include <cstdint>

// Problem dims
#define B_    512
#define T_    128
#define ID_   128
#define HD_   256
#define G4_   1024   // 4*HD
#define OUTD_ 128
#define BT_   65536  // B*T

typedef unsigned long long ull;

// ---------------- scratch (static device globals; no allocation) ----------------
__device__ float g_Wh[2][2][HD_][512];                // [dir][half][k][col] col = gate*128 + hd_local
__device__ float g_bx[2][G4_];                        // bi + bh, natural col order
__device__ float g_gx[2][(size_t)BT_ * G4_];          // precomputed x-gates + bias, 512MB
__device__ float g_x1[(size_t)B_ * T_ * 2 * HD_];
__device__ float g_x2[(size_t)B_ * T_ * HD_];
__device__ float g_x3[(size_t)B_ * T_ * HD_];
__device__ float g_x4[(size_t)B_ * T_ * OUTD_];

// ---------------- helpers ----------------
__device__ __forceinline__ ull fma2(ull a, ull b, ull c) {
    ull d;
    asm("fma.rn.f32x2 %0, %1, %2, %3;" : "=l"(d) : "l"(a), "l"(b), "l"(c));
    return d;
}
__device__ __forceinline__ ull dupf(float v) {
    ull r; unsigned u = __float_as_uint(v);
    asm("mov.b64 %0, {%1, %1};" : "=l"(r) : "r"(u));
    return r;
}
__device__ __forceinline__ ull pack2(float a, float b) {
    ull r;
    asm("mov.b64 %0, {%1, %2};" : "=l"(r) : "r"(__float_as_uint(a)), "r"(__float_as_uint(b)));
    return r;
}
__device__ __forceinline__ float lo32(ull v) { return __uint_as_float((unsigned)v); }
__device__ __forceinline__ float hi32(ull v) { return __uint_as_float((unsigned)(v >> 32)); }
__device__ __forceinline__ float sigm(float x) { return 1.f / (1.f + __expf(-x)); }
__device__ __forceinline__ float tanhp(float x) { return fmaf(2.f, sigm(2.f * x), -1.f); }

#define CLUSTER_SYNC() do { \
    asm volatile("barrier.cluster.arrive.aligned;" ::: "memory"); \
    asm volatile("barrier.cluster.wait.aligned;" ::: "memory"); \
} while (0)

__device__ __forceinline__ void st_cluster64(unsigned addr, ull v) {
    asm volatile("st.shared::cluster.b64 [%0], %1;" :: "r"(addr), "l"(v) : "memory");
}

// ---------------- prep: pack Wh slices + bias sums ----------------
__global__ void prep_kernel(const float* __restrict__ Wh_f, const float* __restrict__ Wh_r,
                            const float* __restrict__ bi_f, const float* __restrict__ bh_f,
                            const float* __restrict__ bi_r, const float* __restrict__ bh_r) {
    int idx = blockIdx.x * blockDim.x + threadIdx.x;
    int stride = gridDim.x * blockDim.x;
    const int total = 2 * 2 * HD_ * 512;
    float* wflat = &g_Wh[0][0][0][0];
    for (int i = idx; i < total; i += stride) {
        int dir = i / (2 * HD_ * 512);
        int r = i % (2 * HD_ * 512);
        int half = r / (HD_ * 512);
        int r2 = r % (HD_ * 512);
        int k = r2 / 512, col = r2 % 512;
        int g = col >> 7, hl = col & 127;
        int sc = g * 256 + half * 128 + hl;
        const float* Wh = dir ? Wh_r : Wh_f;
        wflat[i] = Wh[k * G4_ + sc];
    }
    for (int i = idx; i < 2 * G4_; i += stride) {
        int dir = i >> 10, sc = i & 1023;
        g_bx[dir][sc] = dir ? (bi_r[sc] + bh_r[sc]) : (bi_f[sc] + bh_f[sc]);
    }
}

// ---------------- persistent clustered recurrent LSTM (h @ Wh only) ----------------
// 256 CTAs of 256 threads = 128 clusters of 2 -> 2 independent CTAs per SM
// (decorrelated stalls; one CTA's GEMM covers the other's barrier/update tail).
// Cluster cid: dir = cid>>6, rows = (cid&63)*8..+8. Thread = 2 cols x 8 rows.
#define PREFW(p) { int _p = (p); int _kb = (_p < 64) ? _p * 4 : 252;               \
    const float2* _w = wbase + (size_t)_kb * 256;                                   \
    float2* _d = wv[_p & 3];                                                        \
    _d[0] = _w[0]; _d[1] = _w[256]; _d[2] = _w[512]; _d[3] = _w[768]; }

#define COMP4(bi, rowbase) { const float* _rb = (rowbase);                          \
    _Pragma("unroll") for (int _i = 0; _i < 4; _i++) {                              \
        float2 _w = wv[(bi) & 3][_i];                                               \
        ull w0 = dupf(_w.x), w1 = dupf(_w.y);                                       \
        const ulonglong2* _h = (const ulonglong2*)(_rb + _i * 8);                   \
        ulonglong2 hA = _h[0], hB = _h[1];                                          \
        acc0[0] = fma2(hA.x, w0, acc0[0]); acc1[0] = fma2(hA.x, w1, acc1[0]);       \
        acc0[1] = fma2(hA.y, w0, acc0[1]); acc1[1] = fma2(hA.y, w1, acc1[1]);       \
        acc0[2] = fma2(hB.x, w0, acc0[2]); acc1[2] = fma2(hB.x, w1, acc1[2]);       \
        acc0[3] = fma2(hB.y, w0, acc0[3]); acc1[3] = fma2(hB.y, w1, acc1[3]); } }

__global__ __launch_bounds__(256, 2) __cluster_dims__(2, 1, 1)
void lstm_kernel() {
    extern __shared__ float smem[];
    float* sm_h = smem;                   // [2][256 dims][8 rows] = 16KB ping-pong
    float* sm_g = smem + 4096;            // [8 rows][512 cols] = 16KB

    const int tid = threadIdx.x;
    const int cid = blockIdx.x >> 1;
    const int dir = cid >> 6;
    const int b0 = (cid & 63) * 8;
    unsigned rank;
    asm("mov.u32 %0, %%cluster_ctarank;" : "=r"(rank));
    const int half = (int)rank;

    // gemm-phase mapping: thread = column pair cp (2 cols) x 8 rows
    const int cp = tid;                   // 0..255
    const int c2 = 2 * cp;
    const float2* wbase = (const float2*)(&g_Wh[dir][half][0][0]) + cp;
    // natural (unpermuted) column index of this thread's col pair in gates_x
    const int scg = (c2 >> 7) * 256 + half * 128 + (c2 & 127);
    const float* gxbase = &g_gx[dir][0] + ((size_t)b0 * T_) * G4_ + scg;

    // zero both h parity buffers
    for (int i = tid; i < 4096; i += 256) sm_h[i] = 0.f;

    // update mapping: thread owns dim d for rows rg2*4..+4
    const int d = tid & 127, rg2 = tid >> 7;
    const int ghd = half * 128 + d;
    float cst[4];
#pragma unroll
    for (int j = 0; j < 4; j++) cst[j] = 0.f;

    __syncthreads();
    CLUSTER_SYNC();

#pragma unroll 1
    for (int t = 0; t < T_; t++) {
        const int ts = dir ? (T_ - 1 - t) : t;

        // issue x-gate loads early (consumed at staging, after GEMM)
        float2 gxv[8];
        {
            const float* gp = gxbase + (size_t)ts * G4_;
#pragma unroll
            for (int r = 0; r < 8; r++)
                gxv[r] = *(const float2*)(gp + (size_t)r * T_ * G4_);
        }

        // recurrent GEMM: 8 rows x 2 cols per thread over k=256
        ull acc0[4], acc1[4];
#pragma unroll
        for (int j = 0; j < 4; j++) { acc0[j] = 0ull; acc1[j] = 0ull; }
        float2 wv[4][4];
        PREFW(0); PREFW(1); PREFW(2);
        const float* hb = sm_h + (t & 1) * 2048;
#pragma unroll 4
        for (int ch = 0; ch < 64; ch++) {
            PREFW(ch + 3);
            COMP4(ch, hb + ch * 32);
        }

        // stage gates (+precomputed x-gates incl bias) to sm_g[row][col]
#pragma unroll
        for (int rp = 0; rp < 4; rp++) {
            float2 v0 = make_float2(lo32(acc0[rp]) + gxv[2 * rp].x,
                                    lo32(acc1[rp]) + gxv[2 * rp].y);
            float2 v1 = make_float2(hi32(acc0[rp]) + gxv[2 * rp + 1].x,
                                    hi32(acc1[rp]) + gxv[2 * rp + 1].y);
            *(float2*)&sm_g[(2 * rp) * 512 + c2] = v0;
            *(float2*)&sm_g[(2 * rp + 1) * 512 + c2] = v1;
        }
        __syncthreads();

        // cell update: thread owns hidden dim d (global ghd) for rows rg2*4..+4
        float hv[4];
#pragma unroll
        for (int j = 0; j < 4; j++) {
            const float* gr = sm_g + (rg2 * 4 + j) * 512;
            float f = sigm(gr[d]);
            float ii = sigm(gr[128 + d]);
            float a = tanhp(gr[256 + d]);
            float o = sigm(gr[384 + d]);
            float cc = fmaf(f, cst[j], ii * a);
            cst[j] = cc;
            hv[j] = o * tanhp(cc);
        }

        // h -> own smem (next parity buffer)
        float* hw = sm_h + ((t + 1) & 1) * 2048 + ghd * 8 + rg2 * 4;
        *(float4*)hw = make_float4(hv[0], hv[1], hv[2], hv[3]);
        // h -> peer smem via DSMEM
        {
            unsigned la = (unsigned)__cvta_generic_to_shared(hw);
            unsigned pa;
            asm("mapa.shared::cluster.u32 %0, %1, %2;" : "=r"(pa) : "r"(la), "r"(rank ^ 1u));
            st_cluster64(pa, pack2(hv[0], hv[1]));
            st_cluster64(pa + 8, pack2(hv[2], hv[3]));
        }
        // h -> global x1
        {
            float* gxp = g_x1 + ((size_t)(b0 + rg2 * 4) * T_ + t) * 512 + dir * 256 + ghd;
#pragma unroll
            for (int j = 0; j < 4; j++) gxp[(size_t)j * T_ * 512] = hv[j];
        }

        CLUSTER_SYNC();
    }
}

// ---------------- generic fp32x2 GEMM with bias + optional leaky-relu ----------------
template <int ACT>
__global__ __launch_bounds__(256) void gemm_kernel(const float* __restrict__ A,
                                                   const float* __restrict__ W,
                                                   const float* __restrict__ bias,
                                                   float* __restrict__ C,
                                                   int M, int N, int K) {
    __shared__ __align__(16) float smA[16][64];
    __shared__ __align__(16) float smW[16][128];

    const int tid = threadIdx.x;
    const int n0 = blockIdx.x * 128;
    const int m0 = blockIdx.y * 64;
    const int col = (tid & 31) * 4;
    const int rg = (tid >> 5) * 8;

    ull acc[4][4];
#pragma unroll
    for (int rp = 0; rp < 4; rp++)
#pragma unroll
        for (int c = 0; c < 4; c++) acc[rp][c] = 0ull;

    const int la_r = tid >> 2;
    const int la_k = (tid & 3) * 4;
    const int lw_n = (tid & 31) * 4;
    const int lw_k = tid >> 5;

    for (int k0 = 0; k0 < K; k0 += 16) {
        float4 av = *(const float4*)&A[(size_t)(m0 + la_r) * K + k0 + la_k];
        smA[la_k + 0][la_r] = av.x;
        smA[la_k + 1][la_r] = av.y;
        smA[la_k + 2][la_r] = av.z;
        smA[la_k + 3][la_r] = av.w;
        *(float4*)&smW[lw_k][lw_n]     = *(const float4*)&W[(size_t)(k0 + lw_k) * N + n0 + lw_n];
        *(float4*)&smW[lw_k + 8][lw_n] = *(const float4*)&W[(size_t)(k0 + lw_k + 8) * N + n0 + lw_n];
        __syncthreads();

#pragma unroll
        for (int kk = 0; kk < 16; kk++) {
            float4 wvv = *(const float4*)&smW[kk][col];
            ull wd0 = dupf(wvv.x), wd1 = dupf(wvv.y), wd2 = dupf(wvv.z), wd3 = dupf(wvv.w);
#pragma unroll
            for (int rp = 0; rp < 4; rp++) {
                ull hp = *(const ull*)&smA[kk][rg + 2 * rp];
                acc[rp][0] = fma2(hp, wd0, acc[rp][0]);
                acc[rp][1] = fma2(hp, wd1, acc[rp][1]);
                acc[rp][2] = fma2(hp, wd2, acc[rp][2]);
                acc[rp][3] = fma2(hp, wd3, acc[rp][3]);
            }
        }
        __syncthreads();
    }

    const float4 bv = *(const float4*)&bias[n0 + col];
#pragma unroll
    for (int rp = 0; rp < 4; rp++) {
        const int row0 = m0 + rg + 2 * rp;
        float4 v0, v1;
        v0.x = lo32(acc[rp][0]) + bv.x; v0.y = lo32(acc[rp][1]) + bv.y;
        v0.z = lo32(acc[rp][2]) + bv.z; v0.w = lo32(acc[rp][3]) + bv.w;
        v1.x = hi32(acc[rp][0]) + bv.x; v1.y = hi32(acc[rp][1]) + bv.y;
        v1.z = hi32(acc[rp][2]) + bv.z; v1.w = hi32(acc[rp][3]) + bv.w;
        if (ACT) {
            v0.x = fmaxf(v0.x, 0.1f * v0.x); v0.y = fmaxf(v0.y, 0.1f * v0.y);
            v0.z = fmaxf(v0.z, 0.1f * v0.z); v0.w = fmaxf(v0.w, 0.1f * v0.w);
            v1.x = fmaxf(v1.x, 0.1f * v1.x); v1.y = fmaxf(v1.y, 0.1f * v1.y);
            v1.z = fmaxf(v1.z, 0.1f * v1.z); v1.w = fmaxf(v1.w, 0.1f * v1.w);
        }
        *(float4*)&C[(size_t)row0 * N + n0 + col]       = v0;
        *(float4*)&C[(size_t)(row0 + 1) * N + n0 + col] = v1;
    }
}

// ---------------- head ----------------
__global__ __launch_bounds__(256) void head_kernel(float* __restrict__ out) {
    const int row = blockIdx.x * blockDim.x + threadIdx.x;
    if (row >= B_ * T_) return;
    const float* x = g_x4 + (size_t)row * OUTD_;
    float* o = out + (size_t)row * OUTD_;

#pragma unroll 4
    for (int j = 0; j < 64; j++) o[j] = sigm(x[j]);

    {
        float e[8]; float mx = -1e30f;
#pragma unroll
        for (int j = 0; j < 8; j++) { e[j] = x[64 + j]; mx = fmaxf(mx, e[j]); }
        float ssum = 0.f;
#pragma unroll
        for (int j = 0; j < 8; j++) { e[j] = __expf(e[j] - mx); ssum += e[j]; }
        float inv = 1.f / ssum;
#pragma unroll
        for (int j = 0; j < 8; j++) o[64 + j] = e[j] * inv;
    }
    {
        float e[16]; float mx = -1e30f;
#pragma unroll
        for (int j = 0; j < 16; j++) { e[j] = x[72 + j]; mx = fmaxf(mx, e[j]); }
        float ssum = 0.f;
#pragma unroll
        for (int j = 0; j < 16; j++) { e[j] = __expf(e[j] - mx); ssum += e[j]; }
        float inv = 1.f / ssum;
#pragma unroll
        for (int j = 0; j < 16; j++) o[72 + j] = e[j] * inv;
    }
    {
        float e[40]; float mx = -1e30f;
#pragma unroll
        for (int j = 0; j < 40; j++) { e[j] = x[88 + j]; mx = fmaxf(mx, e[j]); }
        float ssum = 0.f;
#pragma unroll
        for (int j = 0; j < 40; j++) { e[j] = __expf(e[j] - mx); ssum += e[j]; }
        float inv = 1.f / ssum;
#pragma unroll
        for (int j = 0; j < 40; j++) o[88 + j] = e[j] * inv;
    }
}

// ---------------- launch ----------------
extern "C" void kernel_launch(void* const* d_in, const int* in_sizes, int n_in,
                              void* d_out, int out_size) {
    (void)in_sizes; (void)n_in; (void)out_size;
    const float* x0   = (const float*)d_in[0];
    const float* Wi_f = (const float*)d_in[1];
    const float* bi_f = (const float*)d_in[2];
    const float* Wh_f = (const float*)d_in[3];
    const float* bh_f = (const float*)d_in[4];
    const float* Wi_r = (const float*)d_in[5];
    const float* bi_r = (const float*)d_in[6];
    const float* Wh_r = (const float*)d_in[7];
    const float* bh_r = (const float*)d_in[8];
    const float* W1   = (const float*)d_in[9];
    const float* b1   = (const float*)d_in[10];
    const float* W2   = (const float*)d_in[11];
    const float* b2   = (const float*)d_in[12];
    const float* W3   = (const float*)d_in[13];
    const float* b3   = (const float*)d_in[14];
    float* out = (float*)d_out;

    float *p_x1, *p_x2, *p_x3, *p_x4, *p_gx, *p_bx;
    cudaGetSymbolAddress((void**)&p_x1, g_x1);
    cudaGetSymbolAddress((void**)&p_x2, g_x2);
    cudaGetSymbolAddress((void**)&p_x3, g_x3);
    cudaGetSymbolAddress((void**)&p_x4, g_x4);
    cudaGetSymbolAddress((void**)&p_gx, g_gx);
    cudaGetSymbolAddress((void**)&p_bx, g_bx);

    static bool attr_set = false;
    if (!attr_set) {
        cudaFuncSetAttribute(lstm_kernel, cudaFuncAttributeMaxDynamicSharedMemorySize, 32768);
        attr_set = true;
    }

    prep_kernel<<<128, 256>>>(Wh_f, Wh_r, bi_f, bh_f, bi_r, bh_r);

    // precompute x-gates (bias folded): gx[dir] = x0 @ Wi_dir + (bi+bh)
    gemm_kernel<0><<<dim3(G4_ / 128, BT_ / 64), 256>>>(x0, Wi_f, p_bx, p_gx,
                                                       BT_, G4_, ID_);
    gemm_kernel<0><<<dim3(G4_ / 128, BT_ / 64), 256>>>(x0, Wi_r, p_bx + G4_,
                                                       p_gx + (size_t)BT_ * G4_,
                                                       BT_, G4_, ID_);
    lstm_kernel<<<256, 256, 32768>>>();

    const int M = B_ * T_;
    gemm_kernel<1><<<dim3(HD_ / 128, M / 64), 256>>>(p_x1, W1, b1, p_x2, M, HD_, 2 * HD_);
    gemm_kernel<1><<<dim3(HD_ / 128, M / 64), 256>>>(p_x2, W2, b2, p_x3, M, HD_, HD_);
    gemm_kernel<0><<<dim3(OUTD_ / 128, M / 64), 256>>>(p_x3, W3, b3, p_x4, M, OUTD_, HD_);
    head_kernel<<<(M + 255) / 256, 256>>>(out);
}